// round 4
// baseline (speedup 1.0000x reference)
#include <cuda_runtime.h>

// ---------------- problem constants ----------------
#define NB 8
#define NP 2000
#define NC 81
#define NPC 80                    // classes excluding background
#define NM (NP*NPC)               // 160000 candidates per image
#define NROWS (NB*NP)             // 16000 proposal rows
#define KPRE 2048
#define CAPS 16384                // sort capacity
#define NDET 100
#define W_IMG 1333.0f
#define H_IMG 800.0f
#define SCORE_T 0.05f
#define NMS_T 0.5f
#define BBOX_CLIP 4.135166556742356f   // log(1000/16)

// ---------------- device scratch (static, no allocs) ----------------
static __device__ float               g_rmax[NROWS];
static __device__ float               g_rden[NROWS];
static __device__ int                 g_ncand[NB];
static __device__ unsigned long long  g_keys[NB][NM];          // ~10.2 MB
static __device__ unsigned long long  g_pruned[NB][CAPS];
static __device__ int                 g_np[NB];
static __device__ unsigned long long  g_topkey[NB][KPRE];
static __device__ int                 g_ntop[NB];
static __device__ float4              g_topb[NB][KPRE];
static __device__ int                 g_topl[NB][KPRE];
static __device__ float               g_tops[NB][KPRE];
static __device__ unsigned long long  g_sup[NB][KPRE][32];     // 4 MB
static __device__ unsigned long long  g_keep[NB][32];

// ---------------- helpers ----------------
__device__ __forceinline__ float4 decode_box(float4 pr, float r0, float r1, float r2, float r3) {
    float w  = pr.z - pr.x, h  = pr.w - pr.y;
    float cx = pr.x + 0.5f * w, cy = pr.y + 0.5f * h;
    float dx = r0 / 10.0f, dy = r1 / 10.0f;
    float dw = fminf(r2 / 5.0f, BBOX_CLIP);
    float dh = fminf(r3 / 5.0f, BBOX_CLIP);
    float pcx = dx * w + cx, pcy = dy * h + cy;
    float pw  = expf(dw) * w, ph = expf(dh) * h;
    float x1 = pcx - 0.5f * pw, y1 = pcy - 0.5f * ph;
    float x2 = pcx + 0.5f * pw, y2 = pcy + 0.5f * ph;
    x1 = fminf(fmaxf(x1, 0.0f), W_IMG);
    x2 = fminf(fmaxf(x2, 0.0f), W_IMG);
    y1 = fminf(fmaxf(y1, 0.0f), H_IMG);
    y2 = fminf(fmaxf(y2, 0.0f), H_IMG);
    return make_float4(x1, y1, x2, y2);
}

// ---------------- kernel 0: init ----------------
__global__ void k_init() {
    if (threadIdx.x < NB) g_ncand[threadIdx.x] = 0;
}

// ---------------- kernel 1: per-row softmax stats (warp per row) ----------------
__global__ void k_rowstats(const float* __restrict__ logits) {
    int warp = (blockIdx.x * blockDim.x + threadIdx.x) >> 5;
    int lane = threadIdx.x & 31;
    if (warp >= NROWS) return;
    const float* r = logits + (size_t)warp * NC;
    float v0 = r[lane];
    float v1 = r[lane + 32];
    float v2 = (lane < NC - 64) ? r[lane + 64] : -1e30f;
    float mx = fmaxf(v0, fmaxf(v1, v2));
    #pragma unroll
    for (int o = 16; o; o >>= 1) mx = fmaxf(mx, __shfl_xor_sync(0xffffffffu, mx, o));
    float s = expf(v0 - mx) + expf(v1 - mx) + ((lane < NC - 64) ? expf(v2 - mx) : 0.0f);
    #pragma unroll
    for (int o = 16; o; o >>= 1) s += __shfl_xor_sync(0xffffffffu, s, o);
    if (lane == 0) { g_rmax[warp] = mx; g_rden[warp] = s; }
}

// ---------------- kernel 2: threshold + decode + compact keys ----------------
__global__ void k_compact(const float* __restrict__ logits,
                          const float* __restrict__ reg,
                          const float* __restrict__ props) {
    int idx = blockIdx.x * blockDim.x + threadIdx.x;
    if (idx >= NB * NP * NPC) return;
    int b  = idx / (NP * NPC);
    int r2 = idx - b * (NP * NPC);
    int p  = r2 / NPC;
    int cm = r2 - p * NPC;
    int c  = cm + 1;
    int row = b * NP + p;
    float logit = logits[(size_t)row * NC + c];
    float score = expf(logit - g_rmax[row]) / g_rden[row];
    if (!(score > SCORE_T)) return;
    const float* rg = reg + (size_t)row * (NC * 4) + c * 4;
    float4 pr = ((const float4*)props)[row];
    float4 bx = decode_box(pr, rg[0], rg[1], rg[2], rg[3]);
    if ((bx.z - bx.x) >= 0.01f && (bx.w - bx.y) >= 0.01f) {
        int slot = atomicAdd(&g_ncand[b], 1);
        unsigned int sb = __float_as_uint(score);     // score > 0 -> monotone bits
        unsigned long long key =
            (((unsigned long long)(~sb)) << 32) | (unsigned int)(p * NPC + cm);
        g_keys[b][slot] = key;
    }
}

// ---------------- kernel 3: normalize candidates to <= CAPS ----------------
__global__ void k_prune() {
    int b = blockIdx.x;
    int n = g_ncand[b];
    if (n <= CAPS) {
        for (int i = threadIdx.x; i < n; i += blockDim.x) g_pruned[b][i] = g_keys[b][i];
        if (threadIdx.x == 0) g_np[b] = n;
        return;
    }
    __shared__ int hist[4096];
    __shared__ int cutbin;
    __shared__ int outc;
    for (int i = threadIdx.x; i < 4096; i += blockDim.x) hist[i] = 0;
    if (threadIdx.x == 0) outc = 0;
    __syncthreads();
    for (int i = threadIdx.x; i < n; i += blockDim.x) {
        unsigned int inv = (unsigned int)(g_keys[b][i] >> 32);
        int bin = (int)((inv - 0xC0000000u) >> 14);
        bin = min(max(bin, 0), 4095);
        atomicAdd(&hist[bin], 1);
    }
    __syncthreads();
    if (threadIdx.x == 0) {
        int cum = 0, cb = 4095;
        for (int i = 0; i < 4096; i++) { cum += hist[i]; if (cum >= KPRE) { cb = i; break; } }
        cutbin = cb;
    }
    __syncthreads();
    int cb = cutbin;
    for (int i = threadIdx.x; i < n; i += blockDim.x) {
        unsigned long long k = g_keys[b][i];
        unsigned int inv = (unsigned int)(k >> 32);
        int bin = (int)((inv - 0xC0000000u) >> 14);
        bin = min(max(bin, 0), 4095);
        if (bin <= cb) {
            int o = atomicAdd(&outc, 1);
            if (o < CAPS) g_pruned[b][o] = k;
        }
    }
    __syncthreads();
    if (threadIdx.x == 0) g_np[b] = min(outc, CAPS);
}

// ---------------- kernel 4: per-image bitonic sort (shared) ----------------
__global__ void k_sort() {
    extern __shared__ unsigned long long sk[];
    int b = blockIdx.x;
    int n = g_np[b];
    int npad = KPRE;
    while (npad < n) npad <<= 1;     // power of two, >= max(n, 2048), <= CAPS
    for (int i = threadIdx.x; i < npad; i += blockDim.x)
        sk[i] = (i < n) ? g_pruned[b][i] : 0xFFFFFFFFFFFFFFFFull;
    __syncthreads();
    for (int k = 2; k <= npad; k <<= 1) {
        for (int j = k >> 1; j > 0; j >>= 1) {
            for (int t = threadIdx.x; t < npad; t += blockDim.x) {
                int x = t ^ j;
                if (x > t) {
                    unsigned long long a = sk[t], c = sk[x];
                    bool up = ((t & k) == 0);
                    if ((a > c) == up) { sk[t] = c; sk[x] = a; }
                }
            }
            __syncthreads();
        }
    }
    for (int i = threadIdx.x; i < KPRE; i += blockDim.x)
        g_topkey[b][i] = sk[i];
    if (threadIdx.x == 0) g_ntop[b] = min(n, KPRE);
}

// ---------------- kernel 5: re-decode top candidates ----------------
__global__ void k_decode_top(const float* __restrict__ reg,
                             const float* __restrict__ props) {
    int idx = blockIdx.x * blockDim.x + threadIdx.x;
    if (idx >= NB * KPRE) return;
    int b = idx / KPRE, k = idx - b * KPRE;
    if (k >= g_ntop[b]) {
        g_tops[b][k] = -1.0f;
        g_topl[b][k] = 0;
        g_topb[b][k] = make_float4(0.f, 0.f, 0.f, 0.f);
        return;
    }
    unsigned long long key = g_topkey[b][k];
    unsigned int m  = (unsigned int)key;
    unsigned int sb = ~((unsigned int)(key >> 32));
    float score = __uint_as_float(sb);
    int p = m / NPC, cm = m - p * NPC, c = cm + 1;
    int row = b * NP + p;
    const float* rg = reg + (size_t)row * (NC * 4) + c * 4;
    float4 pr = ((const float4*)props)[row];
    float4 bx = decode_box(pr, rg[0], rg[1], rg[2], rg[3]);
    g_tops[b][k] = score;
    g_topl[b][k] = c;
    g_topb[b][k] = bx;
}

// ---------------- kernel 6: suppression bit-matrix ----------------
__global__ void k_mask() {
    int b = blockIdx.x;
    __shared__ float4 sbx[KPRE];
    __shared__ int    sl[KPRE];
    int ntop = g_ntop[b];
    for (int i = threadIdx.x; i < KPRE; i += blockDim.x) {
        sbx[i] = g_topb[b][i];
        sl[i]  = g_topl[b][i];
    }
    __syncthreads();
    int t0 = blockIdx.y * (KPRE * 32 / 8);
    int t1 = t0 + (KPRE * 32 / 8);
    for (int task = t0 + threadIdx.x; task < t1; task += blockDim.x) {
        int i = task >> 5, w = task & 31;
        unsigned long long bits = 0ull;
        if (i < ntop) {
            int j0 = max(w * 64, i + 1), j1 = min(w * 64 + 64, ntop);
            if (j0 < j1) {
                float4 bi = sbx[i];
                int li = sl[i];
                float ai = fmaxf(bi.z - bi.x, 0.f) * fmaxf(bi.w - bi.y, 0.f);
                for (int j = j0; j < j1; j++) {
                    if (sl[j] != li) continue;   // class offset => cross-class IoU = 0
                    float4 bj = sbx[j];
                    float aj = fmaxf(bj.z - bj.x, 0.f) * fmaxf(bj.w - bj.y, 0.f);
                    float ltx = fmaxf(bi.x, bj.x), lty = fmaxf(bi.y, bj.y);
                    float rbx = fminf(bi.z, bj.z), rby = fminf(bi.w, bj.w);
                    float iw = fmaxf(rbx - ltx, 0.f), ih = fmaxf(rby - lty, 0.f);
                    float inter = iw * ih;
                    float uni = ai + aj - inter;
                    float iou = inter / fmaxf(uni, 1e-9f);
                    if (iou > NMS_T) bits |= (1ull << (j - w * 64));
                }
            }
        }
        g_sup[b][i][w] = bits;
    }
}

// ---------------- kernel 7: greedy scan (warp per image, 64-wide blocks) ----------------
__global__ void k_nms() {
    int b = threadIdx.x >> 5;
    int lane = threadIdx.x & 31;
    if (b >= NB) return;
    int ntop = g_ntop[b];
    int base = lane * 64;
    unsigned long long validw =
        (ntop >= base + 64) ? ~0ull : (ntop <= base ? 0ull : ((1ull << (ntop - base)) - 1ull));
    unsigned long long acc = 0ull;       // suppressed bits in my word
    unsigned long long keepmine = 0ull;
    for (int wb = 0; wb < 32; wb++) {
        unsigned long long d0 = g_sup[b][wb * 64 + lane][wb];
        unsigned long long d1 = g_sup[b][wb * 64 + 32 + lane][wb];
        unsigned long long pend = __shfl_sync(0xffffffffu, validw & ~acc, wb);
        unsigned long long kept = 0ull;
        while (pend) {
            int il = __ffsll((long long)pend) - 1;
            kept |= (1ull << il);
            pend &= ~(1ull << il);
            unsigned long long supw =
                __shfl_sync(0xffffffffu, (il < 32) ? d0 : d1, il & 31);
            pend &= ~supw;
        }
        #pragma unroll 4
        for (int il = 0; il < 64; il++) {
            if ((kept >> il) & 1ull) acc |= g_sup[b][wb * 64 + il][lane];
        }
        if (lane == wb) keepmine = kept;
    }
    g_keep[b][lane] = keepmine;
}

// ---------------- kernel 8: finalize top-100 detections ----------------
__global__ void k_final(const float* __restrict__ logits,
                        const float* __restrict__ reg,
                        const float* __restrict__ props,
                        float* __restrict__ out) {
    int b = blockIdx.x;
    __shared__ unsigned long long kw[32];
    __shared__ int kpre[33], npre[33];
    int ntop = g_ntop[b];
    if (threadIdx.x < 32) kw[threadIdx.x] = g_keep[b][threadIdx.x];
    __syncthreads();
    if (threadIdx.x == 0) {
        int ck = 0, cn = 0;
        for (int w = 0; w < 32; w++) {
            kpre[w] = ck; npre[w] = cn;
            int base = w * 64;
            unsigned long long validw = (ntop >= base + 64) ? ~0ull
                : (ntop <= base ? 0ull : ((1ull << (ntop - base)) - 1ull));
            ck += __popcll(kw[w]);
            cn += __popcll(validw & ~kw[w]);
        }
        kpre[32] = ck; npre[32] = cn;
    }
    __syncthreads();
    int nkeep = kpre[32];
    const int OFF_S = NB * NDET * 4;
    const int OFF_L = NB * NDET * 5;
    const int OFF_V = NB * NDET * 6;
    for (int pos = threadIdx.x; pos < KPRE; pos += blockDim.x) {
        if (pos >= ntop) continue;
        int w = pos >> 6, bit = pos & 63;
        bool kept = (kw[w] >> bit) & 1ull;
        unsigned long long below = bit ? (((1ull << bit) - 1ull)) : 0ull;
        int rank;
        if (kept) rank = kpre[w] + __popcll(kw[w] & below);
        else      rank = nkeep + npre[w] + __popcll((~kw[w]) & below);
        if (rank < NDET) {
            int o = b * NDET + rank;
            float4 bx = g_topb[b][pos];
            out[o * 4 + 0] = bx.x; out[o * 4 + 1] = bx.y;
            out[o * 4 + 2] = bx.z; out[o * 4 + 3] = bx.w;
            out[OFF_S + o] = kept ? g_tops[b][pos] : -1.0f;
            out[OFF_L + o] = (float)g_topl[b][pos];
            out[OFF_V + o] = kept ? 1.0f : 0.0f;
        }
    }
    __syncthreads();
    // Pathological filler (ntop < 100): replicate top_k's -1 tie order (smallest invalid m first)
    if (threadIdx.x == 0 && ntop < NDET) {
        int slot = ntop;
        for (int m = 0; m < NM && slot < NDET; m++) {
            int p = m / NPC, cm = m - p * NPC, c = cm + 1;
            int row = b * NP + p;
            float score = expf(logits[(size_t)row * NC + c] - g_rmax[row]) / g_rden[row];
            const float* rg = reg + (size_t)row * (NC * 4) + c * 4;
            float4 pr = ((const float4*)props)[row];
            float4 bx = decode_box(pr, rg[0], rg[1], rg[2], rg[3]);
            bool valid = (score > SCORE_T) && ((bx.z - bx.x) >= 0.01f) && ((bx.w - bx.y) >= 0.01f);
            if (!valid) {
                int o = b * NDET + slot;
                out[o * 4 + 0] = bx.x; out[o * 4 + 1] = bx.y;
                out[o * 4 + 2] = bx.z; out[o * 4 + 3] = bx.w;
                out[OFF_S + o] = -1.0f;
                out[OFF_L + o] = (float)c;
                out[OFF_V + o] = 0.0f;
                slot++;
            }
        }
    }
}

// ---------------- launch ----------------
extern "C" void kernel_launch(void* const* d_in, const int* in_sizes, int n_in,
                              void* d_out, int out_size) {
    const float* logits = nullptr;
    const float* reg    = nullptr;
    const float* props  = nullptr;
    for (int i = 0; i < n_in; i++) {
        if      (in_sizes[i] == NROWS * NC)     logits = (const float*)d_in[i];
        else if (in_sizes[i] == NROWS * NC * 4) reg    = (const float*)d_in[i];
        else if (in_sizes[i] == NROWS * 4)      props  = (const float*)d_in[i];
    }
    float* out = (float*)d_out;

    cudaFuncSetAttribute(k_sort, cudaFuncAttributeMaxDynamicSharedMemorySize, CAPS * 8);

    k_init<<<1, 32>>>();
    k_rowstats<<<(NROWS * 32 + 255) / 256, 256>>>(logits);
    k_compact<<<(NB * NP * NPC + 255) / 256, 256>>>(logits, reg, props);
    k_prune<<<NB, 1024>>>();
    k_sort<<<NB, 1024, CAPS * 8>>>();
    k_decode_top<<<(NB * KPRE + 255) / 256, 256>>>(reg, props);
    k_mask<<<dim3(NB, 8), 1024>>>();
    k_nms<<<1, 256>>>();
    k_final<<<NB, 256>>>(logits, reg, props, out);
}

// round 5
// speedup vs baseline: 2.6663x; 2.6663x over previous
#include <cuda_runtime.h>

// ---------------- problem constants ----------------
#define NB 8
#define NP 2000
#define NC 81
#define NPC 80                    // classes excluding background
#define NM (NP*NPC)               // 160000 candidates per image
#define NROWS (NB*NP)             // 16000 proposal rows
#define KPRE 2048
#define SORTCAP 8192
#define NDET 100
#define W_IMG 1333.0f
#define H_IMG 800.0f
#define SCORE_T 0.05f
#define NMS_T 0.5f
#define BBOX_CLIP 4.135166556742356f   // log(1000/16)

// ---------------- device scratch (static, no allocs) ----------------
static __device__ float               g_rmax[NROWS];
static __device__ float               g_rden[NROWS];
static __device__ int                 g_ncand[NB];
static __device__ unsigned long long  g_keys[NB][NM];          // ~10.2 MB
static __device__ unsigned long long  g_topkey[NB][KPRE];
static __device__ int                 g_ntop[NB];
static __device__ float4              g_topb[NB][KPRE];
static __device__ int                 g_topl[NB][KPRE];
static __device__ float               g_tops[NB][KPRE];
static __device__ unsigned long long  g_sup[NB][KPRE][32];     // 4 MB
static __device__ unsigned long long  g_nz[NB][32];            // per-row "has any suppression" flags
static __device__ unsigned long long  g_keep[NB][32];

// ---------------- helpers ----------------
__device__ __forceinline__ float4 decode_box(float4 pr, float r0, float r1, float r2, float r3) {
    float w  = pr.z - pr.x, h  = pr.w - pr.y;
    float cx = pr.x + 0.5f * w, cy = pr.y + 0.5f * h;
    float dx = r0 / 10.0f, dy = r1 / 10.0f;
    float dw = fminf(r2 / 5.0f, BBOX_CLIP);
    float dh = fminf(r3 / 5.0f, BBOX_CLIP);
    float pcx = dx * w + cx, pcy = dy * h + cy;
    float pw  = expf(dw) * w, ph = expf(dh) * h;
    float x1 = pcx - 0.5f * pw, y1 = pcy - 0.5f * ph;
    float x2 = pcx + 0.5f * pw, y2 = pcy + 0.5f * ph;
    x1 = fminf(fmaxf(x1, 0.0f), W_IMG);
    x2 = fminf(fmaxf(x2, 0.0f), W_IMG);
    y1 = fminf(fmaxf(y1, 0.0f), H_IMG);
    y2 = fminf(fmaxf(y2, 0.0f), H_IMG);
    return make_float4(x1, y1, x2, y2);
}

// ---------------- kernel 1: per-row softmax stats (warp per row) + init ----------------
__global__ void k_rowstats(const float* __restrict__ logits) {
    if (blockIdx.x == 0 && threadIdx.x < NB) g_ncand[threadIdx.x] = 0;
    int warp = (blockIdx.x * blockDim.x + threadIdx.x) >> 5;
    int lane = threadIdx.x & 31;
    if (warp >= NROWS) return;
    const float* r = logits + (size_t)warp * NC;
    float v0 = r[lane];
    float v1 = r[lane + 32];
    float v2 = (lane < NC - 64) ? r[lane + 64] : -1e30f;
    float mx = fmaxf(v0, fmaxf(v1, v2));
    #pragma unroll
    for (int o = 16; o; o >>= 1) mx = fmaxf(mx, __shfl_xor_sync(0xffffffffu, mx, o));
    float s = expf(v0 - mx) + expf(v1 - mx) + ((lane < NC - 64) ? expf(v2 - mx) : 0.0f);
    #pragma unroll
    for (int o = 16; o; o >>= 1) s += __shfl_xor_sync(0xffffffffu, s, o);
    if (lane == 0) { g_rmax[warp] = mx; g_rden[warp] = s; }
}

// ---------------- kernel 2: threshold + decode + compact keys ----------------
__global__ void k_compact(const float* __restrict__ logits,
                          const float* __restrict__ reg,
                          const float* __restrict__ props) {
    int idx = blockIdx.x * blockDim.x + threadIdx.x;
    if (idx >= NB * NP * NPC) return;
    int b  = idx / (NP * NPC);
    int r2 = idx - b * (NP * NPC);
    int p  = r2 / NPC;
    int cm = r2 - p * NPC;
    int c  = cm + 1;
    int row = b * NP + p;
    float logit = logits[(size_t)row * NC + c];
    float score = expf(logit - g_rmax[row]) / g_rden[row];
    if (!(score > SCORE_T)) return;
    const float* rg = reg + (size_t)row * (NC * 4) + c * 4;
    float4 pr = ((const float4*)props)[row];
    float4 bx = decode_box(pr, rg[0], rg[1], rg[2], rg[3]);
    if ((bx.z - bx.x) >= 0.01f && (bx.w - bx.y) >= 0.01f) {
        int slot = atomicAdd(&g_ncand[b], 1);
        unsigned int sb = __float_as_uint(score);     // score > 0 -> monotone bits
        unsigned long long key =
            (((unsigned long long)(~sb)) << 32) | (unsigned int)(p * NPC + cm);
        g_keys[b][slot] = key;
    }
}

// ---------------- kernel 3: histogram select (superset of top-KPRE) + bitonic sort ----------------
// dynamic smem: hist[16384] ints (64KB) | keys[SORTCAP] u64 (64KB) | coarse[1024] ints (4KB)
extern __shared__ unsigned char s_raw[];
__global__ void k_select() {
    int b = blockIdx.x, tid = threadIdx.x;
    int* hist = (int*)s_raw;
    unsigned long long* keys = (unsigned long long*)(s_raw + 65536);
    int* coarse = (int*)(s_raw + 131072);
    __shared__ int s_cutbin, s_outc;
    int n = g_ncand[b];
    for (int i = tid; i < 16384; i += 1024) hist[i] = 0;
    if (tid == 0) s_outc = 0;
    __syncthreads();
    // scores live in (0.05, 1]: float bits [0x3D4CCCCD, 0x3F800000] -> bins [1228, 10240]
    for (int i = tid; i < n; i += 1024) {
        unsigned int sb = ~((unsigned int)(g_keys[b][i] >> 32));
        int bin = (int)((sb - 0x3D000000u) >> 12);
        bin = min(max(bin, 0), 16383);
        atomicAdd(&hist[bin], 1);
    }
    __syncthreads();
    int seg = 0;
    #pragma unroll
    for (int k = 0; k < 16; k++) seg += hist[tid * 16 + k];
    coarse[tid] = seg;
    __syncthreads();
    if (tid == 0) {
        int cum = 0, cb = 0;
        for (int t = 1023; t >= 0; t--) {
            if (cum + coarse[t] >= KPRE) {
                for (int bin = t * 16 + 15; bin >= t * 16; bin--) {
                    cum += hist[bin];
                    if (cum >= KPRE) { cb = bin; break; }
                }
                break;
            }
            cum += coarse[t];
        }
        s_cutbin = cb;   // stays 0 if n < KPRE -> keep everything
    }
    __syncthreads();
    int cb = s_cutbin;
    for (int i = tid; i < n; i += 1024) {
        unsigned long long k = g_keys[b][i];
        unsigned int sb = ~((unsigned int)(k >> 32));
        int bin = (int)((sb - 0x3D000000u) >> 12);
        bin = min(max(bin, 0), 16383);
        if (bin >= cb) {
            int o = atomicAdd(&s_outc, 1);
            if (o < SORTCAP) keys[o] = k;
        }
    }
    __syncthreads();
    int nsel = min(s_outc, SORTCAP);
    int npad = KPRE;
    while (npad < nsel) npad <<= 1;   // typically 4096
    for (int i = tid; i < npad; i += 1024) if (i >= nsel) keys[i] = ~0ull;
    __syncthreads();
    for (int k = 2; k <= npad; k <<= 1) {
        for (int j = k >> 1; j > 0; j >>= 1) {
            for (int t = tid; t < npad; t += 1024) {
                int x = t ^ j;
                if (x > t) {
                    unsigned long long a = keys[t], c = keys[x];
                    bool up = ((t & k) == 0);
                    if ((a > c) == up) { keys[t] = c; keys[x] = a; }
                }
            }
            __syncthreads();
        }
    }
    for (int i = tid; i < KPRE; i += 1024) g_topkey[b][i] = keys[i];
    if (tid == 0) g_ntop[b] = min(nsel, KPRE);
}

// ---------------- kernel 4: re-decode top candidates (+ zero nz flags) ----------------
__global__ void k_decode_top(const float* __restrict__ reg,
                             const float* __restrict__ props) {
    int idx = blockIdx.x * blockDim.x + threadIdx.x;
    if (idx < NB * 32) ((unsigned long long*)g_nz)[idx] = 0ull;
    if (idx >= NB * KPRE) return;
    int b = idx / KPRE, k = idx - b * KPRE;
    if (k >= g_ntop[b]) {
        g_tops[b][k] = -1.0f;
        g_topl[b][k] = 0;
        g_topb[b][k] = make_float4(0.f, 0.f, 0.f, 0.f);
        return;
    }
    unsigned long long key = g_topkey[b][k];
    unsigned int m  = (unsigned int)key;
    unsigned int sb = ~((unsigned int)(key >> 32));
    float score = __uint_as_float(sb);
    int p = m / NPC, cm = m - p * NPC, c = cm + 1;
    int row = b * NP + p;
    const float* rg = reg + (size_t)row * (NC * 4) + c * 4;
    float4 pr = ((const float4*)props)[row];
    float4 bx = decode_box(pr, rg[0], rg[1], rg[2], rg[3]);
    g_tops[b][k] = score;
    g_topl[b][k] = c;
    g_topb[b][k] = bx;
}

// ---------------- kernel 5: suppression bit-matrix (+ nz flags) ----------------
__global__ void k_mask() {
    int b = blockIdx.x;
    __shared__ float4 sbx[KPRE];
    __shared__ int    sl[KPRE];
    int ntop = g_ntop[b];
    for (int i = threadIdx.x; i < KPRE; i += blockDim.x) {
        sbx[i] = g_topb[b][i];
        sl[i]  = g_topl[b][i];
    }
    __syncthreads();
    const int TPS = KPRE * 32 / 16;   // tasks per slice
    int t0 = blockIdx.y * TPS;
    int t1 = t0 + TPS;
    for (int task = t0 + threadIdx.x; task < t1; task += blockDim.x) {
        int i = task >> 5, w = task & 31;
        unsigned long long bits = 0ull;
        if (i < ntop) {
            int j0 = max(w * 64, i + 1), j1 = min(w * 64 + 64, ntop);
            if (j0 < j1) {
                float4 bi = sbx[i];
                int li = sl[i];
                float ai = fmaxf(bi.z - bi.x, 0.f) * fmaxf(bi.w - bi.y, 0.f);
                for (int j = j0; j < j1; j++) {
                    if (sl[j] != li) continue;   // class offset => cross-class IoU = 0
                    float4 bj = sbx[j];
                    float aj = fmaxf(bj.z - bj.x, 0.f) * fmaxf(bj.w - bj.y, 0.f);
                    float ltx = fmaxf(bi.x, bj.x), lty = fmaxf(bi.y, bj.y);
                    float rbx = fminf(bi.z, bj.z), rby = fminf(bi.w, bj.w);
                    float iw = fmaxf(rbx - ltx, 0.f), ih = fmaxf(rby - lty, 0.f);
                    float inter = iw * ih;
                    float uni = ai + aj - inter;
                    float iou = inter / fmaxf(uni, 1e-9f);
                    if (iou > NMS_T) bits |= (1ull << (j - w * 64));
                }
            }
        }
        g_sup[b][i][w] = bits;
        if (bits) atomicOr(&g_nz[b][i >> 6], 1ull << (i & 63));
    }
}

// ---------------- kernel 6: greedy scan, block per image ----------------
// Warps 1-7 double-buffer-stage the next 64-row suppression slab (16KB) into smem
// while warp 0 runs the greedy logic with a ballot-based bulk-keep fast path.
__global__ void k_nms() {
    int b = blockIdx.x;
    int tid = threadIdx.x;
    int warp = tid >> 5, lane = tid & 31;
    __shared__ unsigned long long rows[2][64][32];
    __shared__ unsigned long long s_nz[2];
    __shared__ unsigned long long s_keep[32];
    int ntop = g_ntop[b];

    // stage slab 0 (all threads)
    for (int idx = tid; idx < 2048; idx += 256)
        rows[0][idx >> 5][idx & 31] = g_sup[b][idx >> 5][idx & 31];
    if (tid == 0) s_nz[0] = g_nz[b][0];
    __syncthreads();

    unsigned long long acc = 0ull;      // per-lane (warp0): suppressed bits in word `lane`
    unsigned long long validw = 0ull;
    if (warp == 0) {
        int base = lane * 64;
        validw = (ntop >= base + 64) ? ~0ull
               : (ntop <= base ? 0ull : ((1ull << (ntop - base)) - 1ull));
    }

    for (int wb = 0; wb < 32; wb++) {
        int buf = wb & 1;
        if (warp > 0 && wb + 1 < 32) {
            int nxt = buf ^ 1;
            for (int idx = tid - 32; idx < 2048; idx += 224)
                rows[nxt][idx >> 5][idx & 31] = g_sup[b][(wb + 1) * 64 + (idx >> 5)][idx & 31];
            if (tid == 32) s_nz[nxt] = g_nz[b][wb + 1];
        }
        if (warp == 0) {
            // in-word suppression words for rows lane and lane+32 of this slab
            unsigned long long rl0 = rows[buf][lane][wb];
            unsigned long long rl1 = rows[buf][lane + 32][wb];
            unsigned long long pend = __shfl_sync(0xffffffffu, validw & ~acc, wb);
            unsigned long long nzw = s_nz[buf];
            unsigned long long kept = 0ull;
            while (pend) {
                // does any pending box suppress a later pending box in this word?
                unsigned int c0 = __ballot_sync(0xffffffffu,
                    ((pend >> lane) & 1ull) && (rl0 & pend));
                unsigned int c1 = __ballot_sync(0xffffffffu,
                    ((pend >> (lane + 32)) & 1ull) && (rl1 & pend));
                unsigned long long conf =
                    (unsigned long long)c0 | ((unsigned long long)c1 << 32);
                if (conf == 0ull) {          // bulk path: everything pending is kept
                    kept |= pend;
                    pend = 0ull;
                } else {                     // keep prefix up to first suppressor, apply it
                    int fc = __ffsll((long long)conf) - 1;
                    unsigned long long upto = (fc == 63) ? ~0ull : ((2ull << fc) - 1ull);
                    kept |= pend & upto;
                    unsigned long long rfc = rows[buf][fc][wb];  // broadcast read
                    pend &= ~upto;
                    pend &= ~rfc;
                }
            }
            // fold kept rows with any suppression into acc (all 32 words)
            unsigned long long work = kept & nzw;
            while (work) {
                int il = __ffsll((long long)work) - 1;
                acc |= rows[buf][il][lane];
                work &= work - 1ull;
            }
            if (lane == 0) s_keep[wb] = kept;
        }
        __syncthreads();
    }
    if (tid < 32) g_keep[b][tid] = s_keep[tid];
}

// ---------------- kernel 7: finalize top-100 detections ----------------
__global__ void k_final(const float* __restrict__ logits,
                        const float* __restrict__ reg,
                        const float* __restrict__ props,
                        float* __restrict__ out) {
    int b = blockIdx.x;
    __shared__ unsigned long long kw[32];
    __shared__ int kpre[33], npre[33];
    int ntop = g_ntop[b];
    if (threadIdx.x < 32) kw[threadIdx.x] = g_keep[b][threadIdx.x];
    __syncthreads();
    if (threadIdx.x == 0) {
        int ck = 0, cn = 0;
        for (int w = 0; w < 32; w++) {
            kpre[w] = ck; npre[w] = cn;
            int base = w * 64;
            unsigned long long validw = (ntop >= base + 64) ? ~0ull
                : (ntop <= base ? 0ull : ((1ull << (ntop - base)) - 1ull));
            ck += __popcll(kw[w]);
            cn += __popcll(validw & ~kw[w]);
        }
        kpre[32] = ck; npre[32] = cn;
    }
    __syncthreads();
    int nkeep = kpre[32];
    const int OFF_S = NB * NDET * 4;
    const int OFF_L = NB * NDET * 5;
    const int OFF_V = NB * NDET * 6;
    for (int pos = threadIdx.x; pos < KPRE; pos += blockDim.x) {
        if (pos >= ntop) continue;
        int w = pos >> 6, bit = pos & 63;
        bool kept = (kw[w] >> bit) & 1ull;
        unsigned long long below = bit ? (((1ull << bit) - 1ull)) : 0ull;
        int rank;
        if (kept) rank = kpre[w] + __popcll(kw[w] & below);
        else      rank = nkeep + npre[w] + __popcll((~kw[w]) & below);
        if (rank < NDET) {
            int o = b * NDET + rank;
            float4 bx = g_topb[b][pos];
            out[o * 4 + 0] = bx.x; out[o * 4 + 1] = bx.y;
            out[o * 4 + 2] = bx.z; out[o * 4 + 3] = bx.w;
            out[OFF_S + o] = kept ? g_tops[b][pos] : -1.0f;
            out[OFF_L + o] = (float)g_topl[b][pos];
            out[OFF_V + o] = kept ? 1.0f : 0.0f;
        }
    }
    __syncthreads();
    // Pathological filler (ntop < 100): replicate top_k's -1 tie order (smallest invalid m first)
    if (threadIdx.x == 0 && ntop < NDET) {
        int slot = ntop;
        for (int m = 0; m < NM && slot < NDET; m++) {
            int p = m / NPC, cm = m - p * NPC, c = cm + 1;
            int row = b * NP + p;
            float score = expf(logits[(size_t)row * NC + c] - g_rmax[row]) / g_rden[row];
            const float* rg = reg + (size_t)row * (NC * 4) + c * 4;
            float4 pr = ((const float4*)props)[row];
            float4 bx = decode_box(pr, rg[0], rg[1], rg[2], rg[3]);
            bool valid = (score > SCORE_T) && ((bx.z - bx.x) >= 0.01f) && ((bx.w - bx.y) >= 0.01f);
            if (!valid) {
                int o = b * NDET + slot;
                out[o * 4 + 0] = bx.x; out[o * 4 + 1] = bx.y;
                out[o * 4 + 2] = bx.z; out[o * 4 + 3] = bx.w;
                out[OFF_S + o] = -1.0f;
                out[OFF_L + o] = (float)c;
                out[OFF_V + o] = 0.0f;
                slot++;
            }
        }
    }
}

// ---------------- launch ----------------
extern "C" void kernel_launch(void* const* d_in, const int* in_sizes, int n_in,
                              void* d_out, int out_size) {
    const float* logits = nullptr;
    const float* reg    = nullptr;
    const float* props  = nullptr;
    for (int i = 0; i < n_in; i++) {
        if      (in_sizes[i] == NROWS * NC)     logits = (const float*)d_in[i];
        else if (in_sizes[i] == NROWS * NC * 4) reg    = (const float*)d_in[i];
        else if (in_sizes[i] == NROWS * 4)      props  = (const float*)d_in[i];
    }
    float* out = (float*)d_out;

    static int s_attr_done = 0;
    if (!s_attr_done) {
        cudaFuncSetAttribute(k_select, cudaFuncAttributeMaxDynamicSharedMemorySize, 135168);
        s_attr_done = 1;
    }

    k_rowstats<<<(NROWS * 32 + 255) / 256, 256>>>(logits);
    k_compact<<<(NB * NP * NPC + 255) / 256, 256>>>(logits, reg, props);
    k_select<<<NB, 1024, 135168>>>();
    k_decode_top<<<(NB * KPRE + 255) / 256, 256>>>(reg, props);
    k_mask<<<dim3(NB, 16), 1024>>>();
    k_nms<<<NB, 256>>>();
    k_final<<<NB, 256>>>(logits, reg, props, out);
}

// round 6
// speedup vs baseline: 8.4769x; 3.1793x over previous
#include <cuda_runtime.h>

// ---------------- problem constants ----------------
#define NB 8
#define NP 2000
#define NC 81
#define NPC 80                    // classes excluding background
#define NM (NP*NPC)               // 160000 candidates per image
#define NROWS (NB*NP)             // 16000 proposal rows
#define KPRE 2048
#define SORTCAP 8192
#define NDET 100
#define W_IMG 1333.0f
#define H_IMG 800.0f
#define SCORE_T 0.05f
#define NMS_T 0.5f
#define BBOX_CLIP 4.135166556742356f   // log(1000/16)

// ---------------- device scratch (static, no allocs) ----------------
// counters padded 4KB apart -> different L2 slices, no atomic serialization
static __device__ int                 g_ncand[NB][1024];
static __device__ unsigned long long  g_keys[NB][NM];          // ~10.2 MB
static __device__ int                 g_ntop[NB];
static __device__ float4              g_topb[NB][KPRE];
static __device__ int                 g_topl[NB][KPRE];
static __device__ float               g_tops[NB][KPRE];

// ---------------- helpers ----------------
__device__ __forceinline__ float4 decode_box(float4 pr, float r0, float r1, float r2, float r3) {
    float w  = pr.z - pr.x, h  = pr.w - pr.y;
    float cx = pr.x + 0.5f * w, cy = pr.y + 0.5f * h;
    float dx = r0 / 10.0f, dy = r1 / 10.0f;
    float dw = fminf(r2 / 5.0f, BBOX_CLIP);
    float dh = fminf(r3 / 5.0f, BBOX_CLIP);
    float pcx = dx * w + cx, pcy = dy * h + cy;
    float pw  = expf(dw) * w, ph = expf(dh) * h;
    float x1 = pcx - 0.5f * pw, y1 = pcy - 0.5f * ph;
    float x2 = pcx + 0.5f * pw, y2 = pcy + 0.5f * ph;
    x1 = fminf(fmaxf(x1, 0.0f), W_IMG);
    x2 = fminf(fmaxf(x2, 0.0f), W_IMG);
    y1 = fminf(fmaxf(y1, 0.0f), H_IMG);
    y2 = fminf(fmaxf(y2, 0.0f), H_IMG);
    return make_float4(x1, y1, x2, y2);
}

__device__ __forceinline__ bool iou_gt(float4 a, float4 b) {
    float aa = fmaxf(a.z - a.x, 0.f) * fmaxf(a.w - a.y, 0.f);
    float ab = fmaxf(b.z - b.x, 0.f) * fmaxf(b.w - b.y, 0.f);
    float ltx = fmaxf(a.x, b.x), lty = fmaxf(a.y, b.y);
    float rbx = fminf(a.z, b.z), rby = fminf(a.w, b.w);
    float iw = fmaxf(rbx - ltx, 0.f), ih = fmaxf(rby - lty, 0.f);
    float inter = iw * ih;
    float uni = aa + ab - inter;
    return inter / fmaxf(uni, 1e-9f) > NMS_T;
}

// ========= kernel 1: fused softmax stats + threshold + decode + compact =========
// One warp per proposal row. Threshold tested in logit domain (conservative
// margin, then exact score recheck) so expf runs only for denominator + passers.
__global__ void k_score(const float* __restrict__ logits,
                        const float* __restrict__ reg,
                        const float* __restrict__ props) {
    int gw = (blockIdx.x * blockDim.x + threadIdx.x) >> 5;
    int lane = threadIdx.x & 31;
    if (gw >= NROWS) return;
    int row = gw;
    int b = row / NP;
    int p = row - b * NP;
    const float* lr = logits + (size_t)row * NC;
    float v0 = lr[lane];
    float v1 = lr[lane + 32];
    float v2 = (lane < NC - 64) ? lr[lane + 64] : -1e30f;
    float mx = fmaxf(v0, fmaxf(v1, v2));
    #pragma unroll
    for (int o = 16; o; o >>= 1) mx = fmaxf(mx, __shfl_xor_sync(0xffffffffu, mx, o));
    float den = expf(v0 - mx) + expf(v1 - mx) + ((lane < NC - 64) ? expf(v2 - mx) : 0.0f);
    #pragma unroll
    for (int o = 16; o; o >>= 1) den += __shfl_xor_sync(0xffffffffu, den, o);
    // logit-domain threshold (superset; exact recheck below)
    float lth = mx + logf(SCORE_T * den) - 1e-4f;
    float4 pr = ((const float4*)props)[row];
    #pragma unroll
    for (int it = 0; it < 3; it++) {
        int c = 1 + lane + it * 32;
        bool pass = false;
        unsigned long long key = 0ull;
        if (c <= NPC) {
            float l = lr[c];
            if (l > lth) {
                float score = expf(l - mx) / den;   // exact same expr as reference emulation
                if (score > SCORE_T) {
                    float4 rg = *(const float4*)(reg + (size_t)row * (NC * 4) + c * 4);
                    float4 bx = decode_box(pr, rg.x, rg.y, rg.z, rg.w);
                    if ((bx.z - bx.x) >= 0.01f && (bx.w - bx.y) >= 0.01f) {
                        pass = true;
                        unsigned int sb = __float_as_uint(score);
                        key = (((unsigned long long)(~sb)) << 32)
                            | (unsigned int)(p * NPC + (c - 1));
                    }
                }
            }
        }
        unsigned mask = __ballot_sync(0xffffffffu, pass);
        if (mask) {
            int leader = __ffs(mask) - 1;
            int basec = 0;
            if (lane == leader) basec = atomicAdd(&g_ncand[b][0], __popc(mask));
            basec = __shfl_sync(0xffffffffu, basec, leader);
            if (pass) {
                int slot = basec + __popc(mask & ((1u << lane) - 1u));
                g_keys[b][slot] = key;
            }
        }
    }
}

// ========= kernel 2: histogram select + bitonic sort + decode top =========
// dyn smem: hist[16384] int (64KB) | keys[SORTCAP] u64 (64KB) | coarse[1024] int (4KB)
extern __shared__ unsigned char s_raw[];
__global__ void k_select(const float* __restrict__ reg,
                         const float* __restrict__ props) {
    int b = blockIdx.x, tid = threadIdx.x;
    int* hist = (int*)s_raw;
    unsigned long long* keys = (unsigned long long*)(s_raw + 65536);
    int* coarse = (int*)(s_raw + 131072);
    __shared__ int s_cutbin, s_outc;
    int n = g_ncand[b][0];
    for (int i = tid; i < 16384; i += 1024) hist[i] = 0;
    if (tid == 0) s_outc = 0;
    __syncthreads();
    // scores in (0.05,1]: bits [0x3D4CCCCD,0x3F800000] -> bins [~1228,10240]
    for (int i = tid; i < n; i += 1024) {
        unsigned int sb = ~((unsigned int)(g_keys[b][i] >> 32));
        int bin = (int)((sb - 0x3D000000u) >> 12);
        bin = min(max(bin, 0), 16383);
        atomicAdd(&hist[bin], 1);
    }
    __syncthreads();
    int seg = 0;
    #pragma unroll
    for (int k = 0; k < 16; k++) seg += hist[tid * 16 + k];
    coarse[tid] = seg;
    __syncthreads();
    if (tid == 0) {
        int cum = 0, cb = 0;
        for (int t = 1023; t >= 0; t--) {
            if (cum + coarse[t] >= KPRE) {
                for (int bin = t * 16 + 15; bin >= t * 16; bin--) {
                    cum += hist[bin];
                    if (cum >= KPRE) { cb = bin; break; }
                }
                break;
            }
            cum += coarse[t];
        }
        s_cutbin = cb;   // 0 if n < KPRE -> keep all
    }
    __syncthreads();
    int cb = s_cutbin;
    for (int i = tid; i < n; i += 1024) {
        unsigned long long k = g_keys[b][i];
        unsigned int sb = ~((unsigned int)(k >> 32));
        int bin = (int)((sb - 0x3D000000u) >> 12);
        bin = min(max(bin, 0), 16383);
        if (bin >= cb) {
            int o = atomicAdd(&s_outc, 1);
            if (o < SORTCAP) keys[o] = k;
        }
    }
    __syncthreads();
    int nsel = min(s_outc, SORTCAP);
    int npad = KPRE;
    while (npad < nsel) npad <<= 1;
    for (int i = tid; i < npad; i += 1024) if (i >= nsel) keys[i] = ~0ull;
    __syncthreads();
    for (int k = 2; k <= npad; k <<= 1) {
        for (int j = k >> 1; j > 0; j >>= 1) {
            for (int t = tid; t < npad; t += 1024) {
                int x = t ^ j;
                if (x > t) {
                    unsigned long long a = keys[t], c = keys[x];
                    bool up = ((t & k) == 0);
                    if ((a > c) == up) { keys[t] = c; keys[x] = a; }
                }
            }
            __syncthreads();
        }
    }
    // fused decode of top-KPRE
    int ntop = min(nsel, KPRE);
    for (int k2 = tid; k2 < KPRE; k2 += 1024) {
        if (k2 < ntop) {
            unsigned long long key = keys[k2];
            unsigned int m  = (unsigned int)key;
            unsigned int sb = ~((unsigned int)(key >> 32));
            float score = __uint_as_float(sb);
            int p = m / NPC, cm = m - p * NPC, c = cm + 1;
            int row = b * NP + p;
            float4 rg = *(const float4*)(reg + (size_t)row * (NC * 4) + c * 4);
            float4 pr = ((const float4*)props)[row];
            float4 bx = decode_box(pr, rg.x, rg.y, rg.z, rg.w);
            g_tops[b][k2] = score;
            g_topl[b][k2] = c;
            g_topb[b][k2] = bx;
        } else {
            g_tops[b][k2] = -1.0f;
            g_topl[b][k2] = 0;
            g_topb[b][k2] = make_float4(0.f, 0.f, 0.f, 0.f);
        }
    }
    if (tid == 0) g_ntop[b] = ntop;
}

// ========= kernel 3: fused lazy NMS + finalize =========
// Processes candidates in 64-wide words; computes suppression IoUs lazily:
//  - kept-so-far (<100 while looping) vs current word
//  - 64x64 in-word pairs
// Stops as soon as >=100 boxes are kept (suppression flows forward only, so
// the first 100 kept are final). Fallback (kept<100) walks all words exactly.
__global__ void k_nms(const float* __restrict__ logits,
                      const float* __restrict__ reg,
                      const float* __restrict__ props,
                      float* __restrict__ out) {
    __shared__ float4 kbox[KPRE];
    __shared__ unsigned char klab[KPRE];
    __shared__ short kslot[KPRE];
    __shared__ float4 wbox[64];
    __shared__ int    wlab[64];
    __shared__ unsigned long long inrow[64];
    __shared__ unsigned long long s_sup;
    __shared__ unsigned long long kw[32];
    __shared__ int s_kcount, s_stop;
    __shared__ int npre[33];

    int b = blockIdx.x, tid = threadIdx.x;
    int warp = tid >> 5, lane = tid & 31;
    int ntop = g_ntop[b];
    if (tid == 0) { s_kcount = 0; s_stop = 0; }
    if (tid < 32) kw[tid] = 0ull;
    __syncthreads();

    for (int w = 0; w < 32; w++) {
        int base = w * 64;
        int nword = min(64, ntop - base);
        if (nword <= 0) break;                       // uniform
        if (tid < 64) {
            wbox[tid] = g_topb[b][base + tid];
            wlab[tid] = g_topl[b][base + tid];
            inrow[tid] = 0ull;
        }
        if (tid == 64) s_sup = 0ull;
        __syncthreads();
        int K = s_kcount;
        // earlier-kept vs this word (K < 100 whenever we are still looping)
        for (int idx = tid; idx < K * nword; idx += 256) {
            int i, j;
            if (nword == 64) { i = idx >> 6; j = idx & 63; }
            else             { i = idx / nword; j = idx - i * nword; }
            if ((int)klab[i] == wlab[j] && iou_gt(kbox[i], wbox[j]))
                atomicOr(&s_sup, 1ull << j);
        }
        // in-word pair rows
        for (int idx = tid; idx < 4096; idx += 256) {
            int i = idx >> 6, j = idx & 63;
            if (j > i && j < nword && wlab[i] == wlab[j] && iou_gt(wbox[i], wbox[j]))
                atomicOr(&inrow[i], 1ull << j);
        }
        __syncthreads();
        if (warp == 0) {
            unsigned long long pend =
                ((nword == 64) ? ~0ull : ((1ull << nword) - 1ull)) & ~s_sup;
            unsigned long long r0 = inrow[lane], r1 = inrow[lane + 32];
            unsigned long long kept = 0ull;
            while (pend) {
                unsigned c0 = __ballot_sync(0xffffffffu,
                    ((pend >> lane) & 1ull) && (r0 & pend));
                unsigned c1 = __ballot_sync(0xffffffffu,
                    ((pend >> (lane + 32)) & 1ull) && (r1 & pend));
                unsigned long long conf =
                    (unsigned long long)c0 | ((unsigned long long)c1 << 32);
                if (conf == 0ull) { kept |= pend; break; }
                int fc = __ffsll((long long)conf) - 1;
                unsigned long long upto = (fc == 63) ? ~0ull : ((2ull << fc) - 1ull);
                kept |= pend & upto;
                pend &= ~upto;
                pend &= ~inrow[fc];
            }
            int K0 = s_kcount;
            #pragma unroll
            for (int half = 0; half < 2; half++) {
                int bpos = lane + half * 32;
                if ((kept >> bpos) & 1ull) {
                    unsigned long long below = bpos ? ((1ull << bpos) - 1ull) : 0ull;
                    int pos = K0 + __popcll(kept & below);
                    kbox[pos] = wbox[bpos];
                    klab[pos] = (unsigned char)wlab[bpos];
                    kslot[pos] = (short)(base + bpos);
                }
            }
            if (lane == 0) {
                kw[w] = kept;
                s_kcount = K0 + __popcll(kept);
                if (s_kcount >= NDET) s_stop = 1;
            }
        }
        __syncthreads();
        if (s_stop) break;                            // uniform
    }

    int kcount = s_kcount;
    const int OFF_S = NB * NDET * 4;
    const int OFF_L = NB * NDET * 5;
    const int OFF_V = NB * NDET * 6;
    // kept detections (first min(kcount,100))
    int nk = min(kcount, NDET);
    for (int r = tid; r < nk; r += 256) {
        int slot = kslot[r];
        int o = b * NDET + r;
        float4 bx = kbox[r];
        out[o * 4 + 0] = bx.x; out[o * 4 + 1] = bx.y;
        out[o * 4 + 2] = bx.z; out[o * 4 + 3] = bx.w;
        out[OFF_S + o] = g_tops[b][slot];
        out[OFF_L + o] = (float)klab[r];
        out[OFF_V + o] = 1.0f;
    }
    if (kcount < NDET) {       // uniform condition: all words were processed
        if (tid == 0) {
            int cn = 0;
            for (int ww = 0; ww < 32; ww++) {
                npre[ww] = cn;
                int bb = ww * 64;
                unsigned long long validw = (ntop >= bb + 64) ? ~0ull
                    : (ntop <= bb ? 0ull : ((1ull << (ntop - bb)) - 1ull));
                cn += __popcll(validw & ~kw[ww]);
            }
            npre[32] = cn;
        }
        __syncthreads();
        // non-kept fill in candidate-index order
        for (int pos = tid; pos < ntop; pos += 256) {
            int ww = pos >> 6, bit = pos & 63;
            if ((kw[ww] >> bit) & 1ull) continue;
            unsigned long long below = bit ? ((1ull << bit) - 1ull) : 0ull;
            int rank = kcount + npre[ww] + __popcll((~kw[ww]) & below);
            if (rank < NDET) {
                int o = b * NDET + rank;
                float4 bx = g_topb[b][pos];
                out[o * 4 + 0] = bx.x; out[o * 4 + 1] = bx.y;
                out[o * 4 + 2] = bx.z; out[o * 4 + 3] = bx.w;
                out[OFF_S + o] = -1.0f;
                out[OFF_L + o] = (float)g_topl[b][pos];
                out[OFF_V + o] = 0.0f;
            }
        }
        __syncthreads();
        // pathological filler (ntop < 100): reference top_k -1 tie order
        if (tid == 0 && ntop < NDET) {
            int slot = ntop;
            for (int m = 0; m < NM && slot < NDET; m++) {
                int p = m / NPC, cm = m - p * NPC, c = cm + 1;
                int row = b * NP + p;
                // recompute row softmax stats serially (pathological path only)
                const float* lr = logits + (size_t)row * NC;
                float mx = -1e30f;
                for (int q = 0; q < NC; q++) mx = fmaxf(mx, lr[q]);
                float den = 0.f;
                for (int q = 0; q < NC; q++) den += expf(lr[q] - mx);
                float score = expf(lr[c] - mx) / den;
                const float* rg = reg + (size_t)row * (NC * 4) + c * 4;
                float4 pr = ((const float4*)props)[row];
                float4 bx = decode_box(pr, rg[0], rg[1], rg[2], rg[3]);
                bool valid = (score > SCORE_T) && ((bx.z - bx.x) >= 0.01f)
                           && ((bx.w - bx.y) >= 0.01f);
                if (!valid) {
                    int o = b * NDET + slot;
                    out[o * 4 + 0] = bx.x; out[o * 4 + 1] = bx.y;
                    out[o * 4 + 2] = bx.z; out[o * 4 + 3] = bx.w;
                    out[OFF_S + o] = -1.0f;
                    out[OFF_L + o] = (float)c;
                    out[OFF_V + o] = 0.0f;
                    slot++;
                }
            }
        }
    }
    // reset counter for the next execution (every run ends zeroed)
    if (tid == 0) g_ncand[b][0] = 0;
}

// ---------------- launch ----------------
extern "C" void kernel_launch(void* const* d_in, const int* in_sizes, int n_in,
                              void* d_out, int out_size) {
    const float* logits = nullptr;
    const float* reg    = nullptr;
    const float* props  = nullptr;
    for (int i = 0; i < n_in; i++) {
        if      (in_sizes[i] == NROWS * NC)     logits = (const float*)d_in[i];
        else if (in_sizes[i] == NROWS * NC * 4) reg    = (const float*)d_in[i];
        else if (in_sizes[i] == NROWS * 4)      props  = (const float*)d_in[i];
    }
    float* out = (float*)d_out;

    static int s_attr_done = 0;
    if (!s_attr_done) {
        cudaFuncSetAttribute(k_select, cudaFuncAttributeMaxDynamicSharedMemorySize, 135168);
        s_attr_done = 1;
    }

    k_score<<<(NROWS * 32 + 255) / 256, 256>>>(logits, reg, props);
    k_select<<<NB, 1024, 135168>>>(reg, props);
    k_nms<<<NB, 256>>>(logits, reg, props, out);
}

// round 7
// speedup vs baseline: 21.6421x; 2.5531x over previous
#include <cuda_runtime.h>

// ---------------- problem constants ----------------
#define NB 8
#define NP 2000
#define NC 81
#define NPC 80                    // classes excluding background
#define NM (NP*NPC)               // 160000 candidates per image
#define NROWS (NB*NP)             // 16000 proposal rows
#define KPRE 2048
#define SORTCAP 8192
#define NDET 100
#define W_IMG 1333.0f
#define H_IMG 800.0f
#define SCORE_T 0.05f
#define NMS_T 0.5f
#define BBOX_CLIP 4.135166556742356f   // log(1000/16)

typedef unsigned long long ull;

// ---------------- device scratch (static, no allocs) ----------------
// counters padded 4KB apart -> different L2 slices
static __device__ int  g_ncand[NB][1024];
static __device__ ull  g_keys[NB][NM];          // ~10.2 MB

// ---------------- helpers ----------------
__device__ __forceinline__ float4 decode_box(float4 pr, float r0, float r1, float r2, float r3) {
    float w  = pr.z - pr.x, h  = pr.w - pr.y;
    float cx = pr.x + 0.5f * w, cy = pr.y + 0.5f * h;
    float dx = r0 / 10.0f, dy = r1 / 10.0f;
    float dw = fminf(r2 / 5.0f, BBOX_CLIP);
    float dh = fminf(r3 / 5.0f, BBOX_CLIP);
    float pcx = dx * w + cx, pcy = dy * h + cy;
    float pw  = expf(dw) * w, ph = expf(dh) * h;
    float x1 = pcx - 0.5f * pw, y1 = pcy - 0.5f * ph;
    float x2 = pcx + 0.5f * pw, y2 = pcy + 0.5f * ph;
    x1 = fminf(fmaxf(x1, 0.0f), W_IMG);
    x2 = fminf(fmaxf(x2, 0.0f), W_IMG);
    y1 = fminf(fmaxf(y1, 0.0f), H_IMG);
    y2 = fminf(fmaxf(y2, 0.0f), H_IMG);
    return make_float4(x1, y1, x2, y2);
}

__device__ __forceinline__ bool iou_gt(float4 a, float4 b) {
    float aa = fmaxf(a.z - a.x, 0.f) * fmaxf(a.w - a.y, 0.f);
    float ab = fmaxf(b.z - b.x, 0.f) * fmaxf(b.w - b.y, 0.f);
    float ltx = fmaxf(a.x, b.x), lty = fmaxf(a.y, b.y);
    float rbx = fminf(a.z, b.z), rby = fminf(a.w, b.w);
    float iw = fmaxf(rbx - ltx, 0.f), ih = fmaxf(rby - lty, 0.f);
    float inter = iw * ih;
    float uni = aa + ab - inter;
    return inter / fmaxf(uni, 1e-9f) > NMS_T;
}

// ========= kernel 1: fused softmax stats + threshold + decode + compact =========
__global__ void k_score(const float* __restrict__ logits,
                        const float* __restrict__ reg,
                        const float* __restrict__ props) {
    int gw = (blockIdx.x * blockDim.x + threadIdx.x) >> 5;
    int lane = threadIdx.x & 31;
    if (gw >= NROWS) return;
    int row = gw;
    int b = row / NP;
    int p = row - b * NP;
    const float* lr = logits + (size_t)row * NC;
    float v0 = lr[lane];
    float v1 = lr[lane + 32];
    float v2 = (lane < NC - 64) ? lr[lane + 64] : -1e30f;
    float mx = fmaxf(v0, fmaxf(v1, v2));
    #pragma unroll
    for (int o = 16; o; o >>= 1) mx = fmaxf(mx, __shfl_xor_sync(0xffffffffu, mx, o));
    float den = expf(v0 - mx) + expf(v1 - mx) + ((lane < NC - 64) ? expf(v2 - mx) : 0.0f);
    #pragma unroll
    for (int o = 16; o; o >>= 1) den += __shfl_xor_sync(0xffffffffu, den, o);
    float lth = mx + logf(SCORE_T * den) - 1e-4f;   // conservative logit-domain gate
    float4 pr = ((const float4*)props)[row];
    #pragma unroll
    for (int it = 0; it < 3; it++) {
        int c = 1 + lane + it * 32;
        bool pass = false;
        ull key = 0ull;
        if (c <= NPC) {
            float l = lr[c];
            if (l > lth) {
                float score = expf(l - mx) / den;   // exact recheck
                if (score > SCORE_T) {
                    float4 rg = *(const float4*)(reg + (size_t)row * (NC * 4) + c * 4);
                    float4 bx = decode_box(pr, rg.x, rg.y, rg.z, rg.w);
                    if ((bx.z - bx.x) >= 0.01f && (bx.w - bx.y) >= 0.01f) {
                        pass = true;
                        unsigned int sb = __float_as_uint(score);
                        key = (((ull)(~sb)) << 32) | (unsigned int)(p * NPC + (c - 1));
                    }
                }
            }
        }
        unsigned mask = __ballot_sync(0xffffffffu, pass);
        if (mask) {
            int leader = __ffs(mask) - 1;
            int basec = 0;
            if (lane == leader) basec = atomicAdd(&g_ncand[b][0], __popc(mask));
            basec = __shfl_sync(0xffffffffu, basec, leader);
            if (pass) {
                int slot = basec + __popc(mask & ((1u << lane) - 1u));
                g_keys[b][slot] = key;
            }
        }
    }
}

// ========= kernel 2: fused top-K select + sort + lazy NMS + finalize =========
// dyn smem: hist[16384] int (64KB) | keys[SORTCAP] u64 (64KB) | coarse[1024] int (4KB)
extern __shared__ unsigned char s_raw[];

__global__ __launch_bounds__(1024, 1)
void k_topnms(const float* __restrict__ logits,
              const float* __restrict__ reg,
              const float* __restrict__ props,
              float* __restrict__ out) {
    int b = blockIdx.x, tid = threadIdx.x;
    int warp = tid >> 5, lane = tid & 31;
    int* hist = (int*)s_raw;
    ull* keys = (ull*)(s_raw + 65536);
    int* coarse = (int*)(s_raw + 131072);

    __shared__ int ssum[32];
    __shared__ int s_cb, s_na, s_outc;
    __shared__ float4 wbox[64];
    __shared__ int    wlab[64];
    __shared__ ull    inrow[64];
    __shared__ ull    s_sup;
    __shared__ ull    kw[32];
    __shared__ int    s_kcount, s_stop;
    __shared__ int    npre[33];
    __shared__ float4 kbox[256];
    __shared__ unsigned char klab[256];
    __shared__ float  kscore[256];

    int n = g_ncand[b][0];

    // ---- histogram over score bits (16384 bins, monotone in score) ----
    for (int i = tid; i < 16384; i += 1024) hist[i] = 0;
    __syncthreads();
    for (int i = tid; i < n; i += 1024) {
        unsigned sb = ~((unsigned)(g_keys[b][i] >> 32));
        int bin = min(max((int)((sb - 0x3D000000u) >> 12), 0), 16383);
        atomicAdd(&hist[bin], 1);
    }
    __syncthreads();

    // ---- hierarchical cut finder: cb = smallest bin with count(bins>cb) <= LIMIT ----
    auto find_cut = [&](int LIMIT) {
        int seg = 0;
        #pragma unroll
        for (int k = 0; k < 16; k++) seg += hist[tid * 16 + k];
        coarse[tid] = seg;
        int ws = seg;
        #pragma unroll
        for (int o = 16; o; o >>= 1) ws += __shfl_xor_sync(0xffffffffu, ws, o);
        if (lane == 0) ssum[warp] = ws;
        __syncthreads();
        if (tid == 0) {
            int cum = 0, w = 31;
            while (w >= 0 && cum + ssum[w] <= LIMIT) { cum += ssum[w]; w--; }
            if (w < 0) { s_cb = -1; s_na = cum; }
            else {
                int t = w * 32 + 31;
                while (cum + coarse[t] <= LIMIT) { cum += coarse[t]; t--; }
                int bb = t * 16 + 15;
                while (cum + hist[bb] <= LIMIT) { cum += hist[bb]; bb--; }
                s_cb = bb; s_na = cum;
            }
        }
        __syncthreads();
    };

    // ---- greedy lazy NMS over keys[0..ntop): decode per 64-word on demand ----
    auto run_nms = [&](int ntop) -> int {
        if (tid == 0) { s_kcount = 0; s_stop = 0; }
        if (tid < 32) kw[tid] = 0ull;
        __syncthreads();
        for (int w = 0; w * 64 < ntop; w++) {
            int base = w * 64;
            int nword = min(64, ntop - base);
            if (tid < 64) {
                if (tid < nword) {
                    ull key = keys[base + tid];
                    unsigned m = (unsigned)key;
                    int p = m / NPC, cm = m - p * NPC, c = cm + 1;
                    int row = b * NP + p;
                    float4 rg = *(const float4*)(reg + (size_t)row * (NC * 4) + c * 4);
                    float4 pr = ((const float4*)props)[row];
                    wbox[tid] = decode_box(pr, rg.x, rg.y, rg.z, rg.w);
                    wlab[tid] = c;
                } else wlab[tid] = -1;
                inrow[tid] = 0ull;
            }
            if (tid == 64) s_sup = 0ull;
            __syncthreads();
            int K = s_kcount;
            for (int idx = tid; idx < K * nword; idx += 1024) {
                int i = idx / nword, j = idx - i * nword;
                if ((int)klab[i] == wlab[j] && iou_gt(kbox[i], wbox[j]))
                    atomicOr(&s_sup, 1ull << j);
            }
            for (int idx = tid; idx < 4096; idx += 1024) {
                int i = idx >> 6, j = idx & 63;
                if (j > i && j < nword && wlab[i] == wlab[j] && iou_gt(wbox[i], wbox[j]))
                    atomicOr(&inrow[i], 1ull << j);
            }
            __syncthreads();
            if (warp == 0) {
                ull pend = ((nword == 64) ? ~0ull : ((1ull << nword) - 1ull)) & ~s_sup;
                ull r0 = inrow[lane], r1 = inrow[lane + 32];
                ull kept = 0ull;
                while (pend) {
                    unsigned c0 = __ballot_sync(0xffffffffu,
                        ((pend >> lane) & 1ull) && (r0 & pend));
                    unsigned c1 = __ballot_sync(0xffffffffu,
                        ((pend >> (lane + 32)) & 1ull) && (r1 & pend));
                    ull conf = (ull)c0 | ((ull)c1 << 32);
                    if (!conf) { kept |= pend; break; }
                    int fc = __ffsll((long long)conf) - 1;
                    ull upto = (fc == 63) ? ~0ull : ((2ull << fc) - 1ull);
                    kept |= pend & upto;
                    pend &= ~upto;
                    pend &= ~inrow[fc];
                }
                int K0 = s_kcount;
                #pragma unroll
                for (int half = 0; half < 2; half++) {
                    int bpos = lane + half * 32;
                    if ((kept >> bpos) & 1ull) {
                        ull below = bpos ? ((1ull << bpos) - 1ull) : 0ull;
                        int pos = K0 + __popcll(kept & below);
                        if (pos < 256) {
                            kbox[pos] = wbox[bpos];
                            klab[pos] = (unsigned char)wlab[bpos];
                            kscore[pos] = __uint_as_float(~((unsigned)(keys[base + bpos] >> 32)));
                        }
                    }
                }
                if (lane == 0) {
                    kw[w] = kept;
                    s_kcount = K0 + __popcll(kept);
                    if (s_kcount >= NDET) s_stop = 1;
                }
            }
            __syncthreads();
            if (s_stop) break;                // uniform
        }
        return s_kcount;
    };

    // ================= fast path: exact top-na prefix (na <= 1024) =================
    find_cut(1024);                           // EXCLUSIVE boundary bin -> true prefix
    int cb = s_cb;
    if (tid == 0) s_outc = 0;
    __syncthreads();
    for (int i = tid; i < n; i += 1024) {
        ull k = g_keys[b][i];
        unsigned sb = ~((unsigned)(k >> 32));
        int bin = min(max((int)((sb - 0x3D000000u) >> 12), 0), 16383);
        if (bin > cb) { int o = atomicAdd(&s_outc, 1); keys[o] = k; }
    }
    __syncthreads();
    int na = s_outc;                          // == s_na
    // hybrid bitonic sort of 1024 (1 elem/thread; j<32 stages via shfl, no barrier)
    {
        ull v = (tid < na) ? keys[tid] : ~0ull;
        __syncthreads();
        for (int k = 2; k <= 1024; k <<= 1) {
            for (int j = k >> 1; j; j >>= 1) {
                ull o;
                if (j >= 32) {
                    keys[tid] = v; __syncthreads();
                    o = keys[tid ^ j]; __syncthreads();
                } else {
                    o = __shfl_xor_sync(0xffffffffu, v, j);
                }
                bool up = ((tid & k) == 0);
                bool lower = ((tid & j) == 0);
                ull mn = v < o ? v : o, mx = v < o ? o : v;
                v = (lower == up) ? mn : mx;
            }
        }
        keys[tid] = v;
        __syncthreads();
    }

    int kcount = run_nms(na);
    int ntop = na;

    // ================= fallback: exact top-2048 (rare) =================
    if (kcount < NDET) {
        find_cut(KPRE);                       // inclusive boundary below
        int cb2 = s_cb;
        if (tid == 0) s_outc = 0;
        __syncthreads();
        for (int i = tid; i < n; i += 1024) {
            ull k = g_keys[b][i];
            unsigned sb = ~((unsigned)(k >> 32));
            int bin = min(max((int)((sb - 0x3D000000u) >> 12), 0), 16383);
            if (bin >= cb2) {                 // include boundary bin -> superset of top-2048
                int o = atomicAdd(&s_outc, 1);
                if (o < SORTCAP) keys[o] = k;
            }
        }
        __syncthreads();
        int nsel = min(s_outc, SORTCAP);
        int npad = KPRE;
        while (npad < nsel) npad <<= 1;
        for (int i = tid; i < npad; i += 1024) if (i >= nsel) keys[i] = ~0ull;
        __syncthreads();
        for (int k = 2; k <= npad; k <<= 1) {
            for (int j = k >> 1; j; j >>= 1) {
                for (int t = tid; t < npad; t += 1024) {
                    int x = t ^ j;
                    if (x > t) {
                        ull a = keys[t], c = keys[x];
                        bool up = ((t & k) == 0);
                        if ((a > c) == up) { keys[t] = c; keys[x] = a; }
                    }
                }
                __syncthreads();
            }
        }
        ntop = min(nsel, KPRE);
        kcount = run_nms(ntop);
    }

    // ================= outputs =================
    const int OFF_S = NB * NDET * 4;
    const int OFF_L = NB * NDET * 5;
    const int OFF_V = NB * NDET * 6;
    int nk = min(kcount, NDET);
    for (int r = tid; r < nk; r += 1024) {
        int o = b * NDET + r;
        float4 bx = kbox[r];
        out[o * 4 + 0] = bx.x; out[o * 4 + 1] = bx.y;
        out[o * 4 + 2] = bx.z; out[o * 4 + 3] = bx.w;
        out[OFF_S + o] = kscore[r];
        out[OFF_L + o] = (float)klab[r];
        out[OFF_V + o] = 1.0f;
    }
    if (kcount < NDET) {                      // NMS exhausted -> kw complete
        if (tid == 0) {
            int cn = 0;
            for (int ww = 0; ww < 32; ww++) {
                npre[ww] = cn;
                int bb = ww * 64;
                ull validw = (ntop >= bb + 64) ? ~0ull
                    : (ntop <= bb ? 0ull : ((1ull << (ntop - bb)) - 1ull));
                cn += __popcll(validw & ~kw[ww]);
            }
            npre[32] = cn;
        }
        __syncthreads();
        // non-kept fill in candidate order (score = -1)
        for (int pos = tid; pos < ntop; pos += 1024) {
            int ww = pos >> 6, bit = pos & 63;
            if ((kw[ww] >> bit) & 1ull) continue;
            ull below = bit ? ((1ull << bit) - 1ull) : 0ull;
            int rank = kcount + npre[ww] + __popcll((~kw[ww]) & below);
            if (rank < NDET) {
                ull key = keys[pos];
                unsigned m = (unsigned)key;
                int p = m / NPC, cm = m - p * NPC, c = cm + 1;
                int row = b * NP + p;
                float4 rg = *(const float4*)(reg + (size_t)row * (NC * 4) + c * 4);
                float4 pr = ((const float4*)props)[row];
                float4 bx = decode_box(pr, rg.x, rg.y, rg.z, rg.w);
                int o = b * NDET + rank;
                out[o * 4 + 0] = bx.x; out[o * 4 + 1] = bx.y;
                out[o * 4 + 2] = bx.z; out[o * 4 + 3] = bx.w;
                out[OFF_S + o] = -1.0f;
                out[OFF_L + o] = (float)c;
                out[OFF_V + o] = 0.0f;
            }
        }
        __syncthreads();
        // pathological filler (ntop < 100): reference top_k -1 tie order
        if (tid == 0 && ntop < NDET) {
            int slot = ntop;
            for (int m = 0; m < NM && slot < NDET; m++) {
                int p = m / NPC, cm = m - p * NPC, c = cm + 1;
                int row = b * NP + p;
                const float* lr = logits + (size_t)row * NC;
                float mx = -1e30f;
                for (int q = 0; q < NC; q++) mx = fmaxf(mx, lr[q]);
                float den = 0.f;
                for (int q = 0; q < NC; q++) den += expf(lr[q] - mx);
                float score = expf(lr[c] - mx) / den;
                const float* rg = reg + (size_t)row * (NC * 4) + c * 4;
                float4 pr = ((const float4*)props)[row];
                float4 bx = decode_box(pr, rg[0], rg[1], rg[2], rg[3]);
                bool valid = (score > SCORE_T) && ((bx.z - bx.x) >= 0.01f)
                           && ((bx.w - bx.y) >= 0.01f);
                if (!valid) {
                    int o = b * NDET + slot;
                    out[o * 4 + 0] = bx.x; out[o * 4 + 1] = bx.y;
                    out[o * 4 + 2] = bx.z; out[o * 4 + 3] = bx.w;
                    out[OFF_S + o] = -1.0f;
                    out[OFF_L + o] = (float)c;
                    out[OFF_V + o] = 0.0f;
                    slot++;
                }
            }
        }
    }
    // reset counter for next execution (every run ends zeroed)
    if (tid == 0) g_ncand[b][0] = 0;
}

// ---------------- launch ----------------
extern "C" void kernel_launch(void* const* d_in, const int* in_sizes, int n_in,
                              void* d_out, int out_size) {
    const float* logits = nullptr;
    const float* reg    = nullptr;
    const float* props  = nullptr;
    for (int i = 0; i < n_in; i++) {
        if      (in_sizes[i] == NROWS * NC)     logits = (const float*)d_in[i];
        else if (in_sizes[i] == NROWS * NC * 4) reg    = (const float*)d_in[i];
        else if (in_sizes[i] == NROWS * 4)      props  = (const float*)d_in[i];
    }
    float* out = (float*)d_out;

    static int s_attr_done = 0;
    if (!s_attr_done) {
        cudaFuncSetAttribute(k_topnms, cudaFuncAttributeMaxDynamicSharedMemorySize, 135168);
        s_attr_done = 1;
    }

    k_score<<<(NROWS * 32 + 255) / 256, 256>>>(logits, reg, props);
    k_topnms<<<NB, 1024, 135168>>>(logits, reg, props, out);
}